// round 2
// baseline (speedup 1.0000x reference)
#include <cuda_runtime.h>
#include <math.h>

// Problem constants
#define Bn   32
#define NIc  2048
#define NOc  128
#define TIc  64              // i's per block
#define NTc  (NIc / TIc)     // 32 tiles
#define EPSf 1e-9f
#define LOG2PIf 1.8378770664093453f

#define LAM1 0.0005f         // 0.01*(1-0.95)
#define LAM2 0.000975f       // 0.01*(1-0.95^2)
#define LAM3 0.00142625f     // 0.01*(1-0.95^3)

// Deterministic two-stage reduction scratch (module-static: allocation-free)
// g_part[b][tile][j][33]: [0]=S0, [1..16]=S1(d), [17..32]=S2(d)
__device__ float g_part[(size_t)Bn * NTc * NOc * 33];
// g_stats[b][j][33]: [0..15]=mu, [16..31]=1/sigma2, [32]=L
__device__ float g_stats[(size_t)Bn * NOc * 33];

__device__ __forceinline__ float4 mv4(float4 w, float4 p0, float4 p1, float4 p2, float4 p3) {
    // r[q] = sum_r w[r] * p_r[q]
    float4 r;
    r.x = fmaf(w.x, p0.x, fmaf(w.y, p1.x, fmaf(w.z, p2.x, w.w * p3.x)));
    r.y = fmaf(w.x, p0.y, fmaf(w.y, p1.y, fmaf(w.z, p2.y, w.w * p3.y)));
    r.z = fmaf(w.x, p0.z, fmaf(w.y, p1.z, fmaf(w.z, p2.z, w.w * p3.z)));
    r.w = fmaf(w.x, p0.w, fmaf(w.y, p1.w, fmaf(w.z, p2.w, w.w * p3.w)));
    return r;
}

// ============================================================================
// Pass kernel: recompute votes for a (b, i-tile), form Rp (uniform R for the
// first pass, else recompute R via logp+softmax using g_stats), accumulate
// S0/S1/S2 partials into g_part. Block: 256 threads; thread owns
// j = t>>1 and d in [ (t&1)*8, (t&1)*8+8 ).
// ============================================================================
template <bool UNIFORM>
__global__ __launch_bounds__(256) void pass_kernel(
    const float* __restrict__ pose,   // [B, NI, 4, 4]
    const float* __restrict__ act,    // [B, NI]
    const float* __restrict__ W)      // [NI, NO, 4, 4]
{
    __shared__ float sPose[16];
    __shared__ float sAct[TIc];
    __shared__ float sL[NOc];
    __shared__ float sS[NOc];
    __shared__ float sE[NOc];
    __shared__ float sRed[8];

    const int t    = threadIdx.x;
    const int b    = blockIdx.y;
    const int tile = blockIdx.x;
    const int i0   = tile * TIc;
    const int j    = t >> 1;
    const int h    = t & 1;
    const int d0   = h * 8;

    float mu[8], invs[8];
    if (!UNIFORM) {
        const float* st = g_stats + (size_t)(b * NOc + j) * 33;
        #pragma unroll
        for (int dd = 0; dd < 8; dd++) {
            mu[dd]   = st[d0 + dd];
            invs[dd] = st[16 + d0 + dd];
        }
        if (t < NOc) sL[t] = g_stats[(size_t)(b * NOc + t) * 33 + 32];
    }
    if (t < TIc) sAct[t] = act[b * NIc + i0 + t];

    float a1[8], a2[8];
    #pragma unroll
    for (int dd = 0; dd < 8; dd++) { a1[dd] = 0.f; a2[dd] = 0.f; }
    float s0 = 0.f;

    __syncthreads();

    for (int ii = 0; ii < TIc; ii++) {
        const int i = i0 + ii;
        if (ii) __syncthreads();  // protect sPose reuse across iterations
        if (t < 16) sPose[t] = pose[(size_t)(b * NIc + i) * 16 + t];
        __syncthreads();

        const float4 pr0 = *(const float4*)&sPose[0];
        const float4 pr1 = *(const float4*)&sPose[4];
        const float4 pr2 = *(const float4*)&sPose[8];
        const float4 pr3 = *(const float4*)&sPose[12];

        const float4* Wi = (const float4*)(W + (size_t)i * (NOc * 16));
        const float4 w0 = Wi[j * 4 + h * 2];      // W[i][j][p=h*2][0..3]
        const float4 w1 = Wi[j * 4 + h * 2 + 1];  // W[i][j][p=h*2+1][0..3]

        const float4 va = mv4(w0, pr0, pr1, pr2, pr3);  // v[d0+0..3]
        const float4 vb = mv4(w1, pr0, pr1, pr2, pr3);  // v[d0+4..7]
        float v[8] = {va.x, va.y, va.z, va.w, vb.x, vb.y, vb.z, vb.w};

        float rp;
        if (UNIFORM) {
            rp = sAct[ii] * (1.f / NOc);
        } else {
            // logp quadratic term for this thread's 8 d's
            float qs = 0.f;
            #pragma unroll
            for (int dd = 0; dd < 8; dd++) {
                const float df = v[dd] - mu[dd];
                qs = fmaf(df * df, invs[dd], qs);
            }
            qs += __shfl_xor_sync(0xffffffffu, qs, 1);  // combine both d-halves of j
            if (!h) sS[j] = sL[j] - 0.5f * qs;
            __syncthreads();

            // softmax over j = 0..127 (threads 0..127 hold one logit each)
            const float x = (t < NOc) ? sS[t] : -3.0e38f;
            float m = x;
            #pragma unroll
            for (int off = 16; off; off >>= 1)
                m = fmaxf(m, __shfl_xor_sync(0xffffffffu, m, off));
            if (t < NOc && !(t & 31)) sRed[t >> 5] = m;
            __syncthreads();
            const float M = fmaxf(fmaxf(sRed[0], sRed[1]), fmaxf(sRed[2], sRed[3]));
            float e = (t < NOc) ? __expf(x - M) : 0.f;
            if (t < NOc) sE[t] = e;
            float sm = e;
            #pragma unroll
            for (int off = 16; off; off >>= 1)
                sm += __shfl_xor_sync(0xffffffffu, sm, off);
            if (t < NOc && !(t & 31)) sRed[4 + (t >> 5)] = sm;
            __syncthreads();
            const float T = sRed[4] + sRed[5] + sRed[6] + sRed[7];
            rp = sE[j] * __fdividef(sAct[ii], T);  // R_new * a_in
        }

        if (!h) s0 += rp;
        #pragma unroll
        for (int dd = 0; dd < 8; dd++) {
            const float rv = rp * v[dd];
            a1[dd] += rv;
            a2[dd] = fmaf(rv, v[dd], a2[dd]);
        }
    }

    // write block partials (contiguous 33-float row per j) — near-coalesced
    float* pb = g_part + ((size_t)(b * NTc + tile) * NOc + j) * 33;
    if (!h) pb[0] = s0;
    #pragma unroll
    for (int dd = 0; dd < 8; dd++) {
        pb[1 + d0 + dd]  = a1[dd];
        pb[17 + d0 + dd] = a2[dd];
    }
}

// ============================================================================
// Stats kernel: one warp per (b, j). Lane = stat-index k (0..31, plus k=32
// carried by lane 0); loop over the 32 tiles with coalesced 132B reads and
// reduce in-register. Then gather S1[d]/S2[d] via 2 shuffles and compute
// mu / sigma2 / a_out (and L, 1/sigma2 for the next pass, or final outputs).
// ============================================================================
template <bool FINAL>
__global__ __launch_bounds__(256) void stats_kernel(
    const float* __restrict__ beta_v,
    const float* __restrict__ beta_a,
    float lam,
    float* __restrict__ out)
{
    const int warp = (blockIdx.x * blockDim.x + threadIdx.x) >> 5;  // 0..4095
    const int lane = threadIdx.x & 31;
    const int b = warp >> 7;
    const int j = warp & 127;

    const float* base = g_part + ((size_t)b * NTc * NOc + j) * 33;
    float acc = 0.f;    // sum over tiles of stat k=lane
    float acc2 = 0.f;   // lane 0 also carries k=32
    #pragma unroll 4
    for (int tile = 0; tile < NTc; tile++) {
        const float* row = base + (size_t)tile * NOc * 33;
        acc += row[lane];
        if (lane == 0) acc2 += row[32];
    }

    const float S0 = __shfl_sync(0xffffffffu, acc, 0);
    const int d = lane & 15;
    const float S1d = __shfl_sync(0xffffffffu, acc, 1 + d);
    const float s2lo = __shfl_sync(0xffffffffu, acc, (17 + d) & 31);
    const float s2hi = __shfl_sync(0xffffffffu, acc2, 0);
    const float S2d = (d == 15) ? s2hi : s2lo;

    const float Rs = S0 + EPSf;
    const float invRs = 1.f / Rs;
    const float muv = S1d * invRs;
    // sum Rp*(v-mu)^2 = S2 - 2*mu*S1 + mu^2*S0  (exact expansion)
    const float srp = S2d - 2.f * muv * S1d + muv * muv * S0;
    const float sig = srp * invRs + EPSf;
    const float lg  = logf(sig);
    float logsum = lg;
    #pragma unroll
    for (int off = 8; off; off >>= 1)
        logsum += __shfl_xor_sync(0xffffffffu, logsum, off);

    const float cost = (16.f * beta_v[j] + 0.5f * logsum) * Rs;
    const float aout = 1.f / (1.f + expf(-(lam * (beta_a[j] - cost))));

    if (FINAL) {
        if (lane < 16) out[(size_t)(b * NOc + j) * 16 + d] = muv;        // pose_out
        if (lane == 0) out[(size_t)Bn * NOc * 16 + b * NOc + j] = aout;  // a_out
    } else {
        float* st = g_stats + (size_t)(b * NOc + j) * 33;
        if (lane < 16) {
            st[d]      = muv;
            st[16 + d] = 1.f / sig;
        }
        if (lane == 0)
            st[32] = logf(aout + EPSf) - 0.5f * logsum - 8.f * LOG2PIf;
    }
}

extern "C" void kernel_launch(void* const* d_in, const int* in_sizes, int n_in,
                              void* d_out, int out_size) {
    const float* pose   = (const float*)d_in[0];   // [32, 2048, 4, 4]
    const float* act    = (const float*)d_in[1];   // [32, 2048]
    const float* W      = (const float*)d_in[2];   // [2048, 128, 4, 4]
    const float* beta_v = (const float*)d_in[3];   // [128]
    const float* beta_a = (const float*)d_in[4];   // [128]
    float* out = (float*)d_out;                    // pose_out (65536) ++ a_out (4096)

    dim3 gp(NTc, Bn);                         // 32 x 32 blocks, 256 threads
    const int sgrid = (Bn * NOc * 32) / 256;  // 512 blocks, warp per (b,j)

    // t=0: uniform R
    pass_kernel<true><<<gp, 256>>>(pose, act, W);
    stats_kernel<false><<<sgrid, 256>>>(beta_v, beta_a, LAM1, out);
    // t=1: R from stats0, accumulate
    pass_kernel<false><<<gp, 256>>>(pose, act, W);
    stats_kernel<false><<<sgrid, 256>>>(beta_v, beta_a, LAM2, out);
    // t=2: R from stats1, accumulate; final stats write outputs
    pass_kernel<false><<<gp, 256>>>(pose, act, W);
    stats_kernel<true><<<sgrid, 256>>>(beta_v, beta_a, LAM3, out);
}